// round 13
// baseline (speedup 1.0000x reference)
#include <cuda_runtime.h>
#include <cuda_bf16.h>
#include <math.h>
#include <stdint.h>

// Problem constants
#define BB 512
#define TT 1024
#define FF 128
#define UU 50
#define GG 200            // 4*U gate columns
#define NROWS (BB * TT)   // 524288 GEMM rows
#define MT32 (NROWS / 32) // 16384 m32 tiles
#define NCTA_P 288        // proj CTAs (2 per SM, 3 N-groups x 96)
#define WSTRIDE_P (96 * 8)// m32-tile warp stride per N-group

// Scratch: xproj[b*T + t][200] = x[b,t,:] @ kernel (fp32)
__device__ float g_xproj[(size_t)NROWS * GG];

// ---------------------------------------------------------------------------
// helpers
// ---------------------------------------------------------------------------
__device__ __forceinline__ uint32_t smem_u32(const void* p) {
    uint32_t a;
    asm("{ .reg .u64 t; cvta.to.shared.u64 t, %1; cvt.u32.u64 %0, t; }" : "=r"(a) : "l"(p));
    return a;
}

__device__ __forceinline__ uint32_t bf2pack(float a, float b) {
    __nv_bfloat162 t = __floats2bfloat162_rn(a, b);
    return *reinterpret_cast<uint32_t*>(&t);
}

// pack top 16 bits of two floats into bf16x2 (truncation split, 1 instr)
__device__ __forceinline__ uint32_t hipack(float a, float b) {
    uint32_t d;
    asm("prmt.b32 %0, %1, %2, 0x7632;" : "=r"(d)
        : "r"(__float_as_uint(a)), "r"(__float_as_uint(b)));
    return d;
}
__device__ __forceinline__ float trunc_hi(float v) {
    return __uint_as_float(__float_as_uint(v) & 0xffff0000u);
}

__device__ __forceinline__ void mma16816(float* d, uint32_t a0, uint32_t a1,
                                         uint32_t a2, uint32_t a3,
                                         uint32_t b0, uint32_t b1) {
    asm volatile(
        "mma.sync.aligned.m16n8k16.row.col.f32.bf16.bf16.f32 "
        "{%0,%1,%2,%3}, {%4,%5,%6,%7}, {%8,%9}, {%0,%1,%2,%3};"
        : "+f"(d[0]), "+f"(d[1]), "+f"(d[2]), "+f"(d[3])
        : "r"(a0), "r"(a1), "r"(a2), "r"(a3), "r"(b0), "r"(b1));
}

__device__ __forceinline__ void ldsm_x4(uint32_t& r0, uint32_t& r1,
                                        uint32_t& r2, uint32_t& r3, uint32_t addr) {
    asm volatile("ldmatrix.sync.aligned.m8n8.x4.shared.b16 {%0,%1,%2,%3}, [%4];"
                 : "=r"(r0), "=r"(r1), "=r"(r2), "=r"(r3) : "r"(addr));
}

// packed fp32x2 ops
__device__ __forceinline__ void fma2(uint64_t& d, uint64_t a, uint64_t b) {
    asm("fma.rn.f32x2 %0, %1, %2, %0;" : "+l"(d) : "l"(a), "l"(b));
}
__device__ __forceinline__ void add2(uint64_t& d, uint64_t a) {
    asm("add.rn.f32x2 %0, %0, %1;" : "+l"(d) : "l"(a));
}
__device__ __forceinline__ uint64_t pk2(float lo, float hi) {
    uint64_t r;
    asm("mov.b64 %0, {%1, %2};" : "=l"(r) : "f"(lo), "f"(hi));
    return r;
}
__device__ __forceinline__ void up2(float& lo, float& hi, uint64_t v) {
    asm("mov.b64 {%0, %1}, %2;" : "=f"(lo), "=f"(hi) : "l"(v));
}

__device__ __forceinline__ float fast_tanh(float v) {
    float y;
    asm("tanh.approx.f32 %0, %1;" : "=f"(y) : "f"(v));
    return y;
}
__device__ __forceinline__ float fast_sig(float v) {
    return fmaf(fast_tanh(0.5f * v), 0.5f, 0.5f);
}

// ---------------------------------------------------------------------------
// Kernel 1: projection GEMM xproj = x @ W via HMMA bf16, 3-term hi/lo split.
//   288 CTAs x 256 threads; 3 N-groups; each warp owns an m32 tile with
//   B-fragment reuse across the two m16 halves. [R9-measured: 278.8us]
// ---------------------------------------------------------------------------
#define NT 9                         // n-tiles per CTA group
#define NBROWS (NT * 8)              // 72 B rows staged
#define KP 136                       // padded B row stride in bf16
#define BROW (KP * 2)                // 272 bytes
#define SMB_LO (NBROWS * BROW)       // 19584
#define SMB_TOTAL (2 * NBROWS * BROW)// 39168 bytes

__global__ __launch_bounds__(256, 2)
void proj_kernel(const float* __restrict__ x, const float* __restrict__ W) {
    extern __shared__ char smem[];
    const uint32_t sb = smem_u32(smem);
    const int tid = threadIdx.x;
    const int wid = tid >> 5;
    const int lane = tid & 31;
    const int grpN = blockIdx.x % 3;
    const int noff = grpN * 64;       // global n float-offset of this slice

    for (int idx = tid; idx < NBROWS * FF; idx += 256) {
        int nl = idx >> 7;
        int k = idx & 127;
        float v = W[k * GG + (noff + nl)];
        __nv_bfloat16 hi = __float2bfloat16_rn(v);
        float lo = v - __bfloat162float(hi);
        uint32_t off = (uint32_t)(nl * BROW + k * 2);
        *reinterpret_cast<__nv_bfloat16*>(smem + off) = hi;
        *reinterpret_cast<__nv_bfloat16*>(smem + SMB_LO + off) = __float2bfloat16_rn(lo);
    }
    __syncthreads();

    const int l8 = lane & 7;
    const int grp = lane >> 3;
    const uint32_t lmOff = (uint32_t)(l8 * BROW + (grp & 1) * 16 + (grp >> 1) * SMB_LO);

    const int r = lane >> 2;
    const int cq = lane & 3;

    for (int mt = (blockIdx.x / 3) * 8 + wid; mt < MT32; mt += WSTRIDE_P) {
        const size_t row0 = (size_t)mt * 32 + r;

        const float* __restrict__ p0 = x + row0 * FF;
        const float* __restrict__ p1 = x + (row0 + 8) * FF;
        const float* __restrict__ p2 = x + (row0 + 16) * FF;
        const float* __restrict__ p3 = x + (row0 + 24) * FF;

        float acc0[NT][4], acc1[NT][4];
#pragma unroll
        for (int j = 0; j < NT; ++j) {
#pragma unroll
            for (int q = 0; q < 4; ++q) { acc0[j][q] = 0.f; acc1[j][q] = 0.f; }
        }

#pragma unroll
        for (int kk = 0; kk < 8; ++kk) {
            const int k0 = kk * 16;
            float2 f0 = *(const float2*)(p0 + k0 + 2 * cq);
            float2 f1 = *(const float2*)(p1 + k0 + 2 * cq);
            float2 f2 = *(const float2*)(p0 + k0 + 2 * cq + 8);
            float2 f3 = *(const float2*)(p1 + k0 + 2 * cq + 8);
            float2 g0 = *(const float2*)(p2 + k0 + 2 * cq);
            float2 g1 = *(const float2*)(p3 + k0 + 2 * cq);
            float2 g2 = *(const float2*)(p2 + k0 + 2 * cq + 8);
            float2 g3 = *(const float2*)(p3 + k0 + 2 * cq + 8);

            uint32_t ah0 = hipack(f0.x, f0.y), ah1 = hipack(f1.x, f1.y);
            uint32_t ah2 = hipack(f2.x, f2.y), ah3 = hipack(f3.x, f3.y);
            uint32_t al0 = bf2pack(f0.x - trunc_hi(f0.x), f0.y - trunc_hi(f0.y));
            uint32_t al1 = bf2pack(f1.x - trunc_hi(f1.x), f1.y - trunc_hi(f1.y));
            uint32_t al2 = bf2pack(f2.x - trunc_hi(f2.x), f2.y - trunc_hi(f2.y));
            uint32_t al3 = bf2pack(f3.x - trunc_hi(f3.x), f3.y - trunc_hi(f3.y));

            uint32_t bh0_ = hipack(g0.x, g0.y), bh1_ = hipack(g1.x, g1.y);
            uint32_t bh2_ = hipack(g2.x, g2.y), bh3_ = hipack(g3.x, g3.y);
            uint32_t bl0_ = bf2pack(g0.x - trunc_hi(g0.x), g0.y - trunc_hi(g0.y));
            uint32_t bl1_ = bf2pack(g1.x - trunc_hi(g1.x), g1.y - trunc_hi(g1.y));
            uint32_t bl2_ = bf2pack(g2.x - trunc_hi(g2.x), g2.y - trunc_hi(g2.y));
            uint32_t bl3_ = bf2pack(g3.x - trunc_hi(g3.x), g3.y - trunc_hi(g3.y));

            const uint32_t kOff = sb + (uint32_t)(k0 * 2) + lmOff;
#pragma unroll
            for (int j = 0; j < NT; ++j) {
                uint32_t wh0, wh1, wl0, wl1;
                ldsm_x4(wh0, wh1, wl0, wl1, kOff + (uint32_t)(j * 8 * BROW));
                mma16816(acc0[j], ah0, ah1, ah2, ah3, wh0, wh1);
                mma16816(acc0[j], ah0, ah1, ah2, ah3, wl0, wl1);
                mma16816(acc0[j], al0, al1, al2, al3, wh0, wh1);
                mma16816(acc1[j], bh0_, bh1_, bh2_, bh3_, wh0, wh1);
                mma16816(acc1[j], bh0_, bh1_, bh2_, bh3_, wl0, wl1);
                mma16816(acc1[j], bl0_, bl1_, bl2_, bl3_, wh0, wh1);
            }
        }

        float* __restrict__ d0 = g_xproj + row0 * GG + noff + 2 * cq;
        float* __restrict__ d1 = d0 + 8 * GG;
        float* __restrict__ d2 = d0 + 16 * GG;
        float* __restrict__ d3 = d0 + 24 * GG;
#pragma unroll
        for (int j = 0; j < NT; ++j) {
            *(float2*)(d0 + j * 8) = make_float2(acc0[j][0], acc0[j][1]);
            *(float2*)(d1 + j * 8) = make_float2(acc0[j][2], acc0[j][3]);
            *(float2*)(d2 + j * 8) = make_float2(acc1[j][0], acc1[j][1]);
            *(float2*)(d3 + j * 8) = make_float2(acc1[j][2], acc1[j][3]);
        }
    }
}

// ---------------------------------------------------------------------------
// Kernel 2: LSTM recurrence, f32x2 QUAD-ROW: rows (A,B) and (C,D) each
//   packed element-wise into f32x2 lanes, sharing one set of duplicated
//   weight registers. 128 CTAs x 224 threads (1/SM, single wave).
//   Per step: 100 fma2 (8 chains), 4 LDG prefetches, 2 barriers = 0.5/row.
//   Update split: tid<50 -> rows A,B; tid 64..113 -> rows C,D.
// ---------------------------------------------------------------------------
__global__ __launch_bounds__(224)
void lstm_kernel(const float* __restrict__ R, const float* __restrict__ bias,
                 const float* __restrict__ dw, const float* __restrict__ db,
                 float* __restrict__ out) {
    __shared__ __align__(16) float hAB_s[104];   // pairs (hA[k],hB[k])
    __shared__ __align__(16) float hCD_s[104];   // pairs (hC[k],hD[k])
    __shared__ __align__(16) float zA_s[224], zB_s[224], zC_s[224], zD_s[224];

    const int tid = threadIdx.x;
    const int b0 = blockIdx.x * 4;
    const int g = tid & 3;            // gate: 0=i 1=f 2=g~ 3=o
    const int u = tid >> 2;           // unit
    int col = g * 50 + u;
    if (col > 199) col = 199;         // threads 200..223: harmless clamp

    uint64_t rw[UU];                  // duplicated weights (w_k, w_k)
#pragma unroll
    for (int k = 0; k < UU; ++k) {
        float w = R[k * GG + col];
        rw[k] = pk2(w, w);
    }
    const float bv = bias[col];

    for (int i = tid; i < 104; i += 224) { hAB_s[i] = 0.f; hCD_s[i] = 0.f; }
    float c0 = 0.f, c1 = 0.f;   // (cA,cB) in group-1 threads, (cC,cD) in group-2
    __syncthreads();

    const float* __restrict__ xpA = g_xproj + (size_t)b0 * TT * GG;
    const float* __restrict__ xpB = xpA + (size_t)TT * GG;
    const float* __restrict__ xpC = xpB + (size_t)TT * GG;
    const float* __restrict__ xpD = xpC + (size_t)TT * GG;
    float xvA = __ldcs(xpA + col), xvB = __ldcs(xpB + col);
    float xvC = __ldcs(xpC + col), xvD = __ldcs(xpD + col);

#pragma unroll 1
    for (int t = 0; t < TT; ++t) {
        const size_t toff = (size_t)((t + 1 < TT) ? (t + 1) : (TT - 1)) * GG + col;
        float xnA = __ldcs(xpA + toff);
        float xnB = __ldcs(xpB + toff);
        float xnC = __ldcs(xpC + toff);
        float xnD = __ldcs(xpD + toff);

        // quad-row dot: 100 fma2 over pair arrays, 8 independent chains
        uint64_t z2 = pk2(0.f, 0.f);
        uint64_t p0 = z2, p1 = z2, p2 = z2, p3 = z2;   // AB chains
        uint64_t q0 = z2, q1 = z2, q2 = z2, q3 = z2;   // CD chains
#pragma unroll
        for (int i = 0; i < 12; ++i) {
            ulonglong2 a01 = *(const ulonglong2*)(hAB_s + 8 * i);
            ulonglong2 a23 = *(const ulonglong2*)(hAB_s + 8 * i + 4);
            ulonglong2 c01 = *(const ulonglong2*)(hCD_s + 8 * i);
            ulonglong2 c23 = *(const ulonglong2*)(hCD_s + 8 * i + 4);
            fma2(p0, rw[4 * i + 0], a01.x);
            fma2(p1, rw[4 * i + 1], a01.y);
            fma2(p2, rw[4 * i + 2], a23.x);
            fma2(p3, rw[4 * i + 3], a23.y);
            fma2(q0, rw[4 * i + 0], c01.x);
            fma2(q1, rw[4 * i + 1], c01.y);
            fma2(q2, rw[4 * i + 2], c23.x);
            fma2(q3, rw[4 * i + 3], c23.y);
        }
        {
            ulonglong2 at = *(const ulonglong2*)(hAB_s + 96);
            ulonglong2 ct = *(const ulonglong2*)(hCD_s + 96);
            fma2(p0, rw[48], at.x); fma2(p1, rw[49], at.y);
            fma2(q0, rw[48], ct.x); fma2(q1, rw[49], ct.y);
        }
        add2(p0, p1); add2(p2, p3); add2(p0, p2);
        add2(q0, q1); add2(q2, q3); add2(q0, q2);
        float sA, sB, sC, sD;
        up2(sA, sB, p0);
        up2(sC, sD, q0);
        sA += bv + xvA; sB += bv + xvB;
        sC += bv + xvC; sD += bv + xvD;

        if (g == 2) {
            zA_s[tid] = fast_tanh(sA); zB_s[tid] = fast_tanh(sB);
            zC_s[tid] = fast_tanh(sC); zD_s[tid] = fast_tanh(sD);
        } else {
            zA_s[tid] = fast_sig(sA);  zB_s[tid] = fast_sig(sB);
            zC_s[tid] = fast_sig(sC);  zD_s[tid] = fast_sig(sD);
        }
        __syncthreads();

        if (tid < UU) {                       // group 1: rows A,B
            float4 za = *(const float4*)(zA_s + 4 * tid);
            float4 zb = *(const float4*)(zB_s + 4 * tid);
            c0 = fmaf(za.y, c0, za.x * za.z);
            c1 = fmaf(zb.y, c1, zb.x * zb.z);
            *(float2*)(hAB_s + 2 * tid) =
                make_float2(za.w * fast_tanh(c0), zb.w * fast_tanh(c1));
        } else if (tid >= 64 && tid < 64 + UU) { // group 2: rows C,D
            int v = tid - 64;
            float4 zc = *(const float4*)(zC_s + 4 * v);
            float4 zd = *(const float4*)(zD_s + 4 * v);
            c0 = fmaf(zc.y, c0, zc.x * zc.z);
            c1 = fmaf(zd.y, c1, zd.x * zd.z);
            *(float2*)(hCD_s + 2 * v) =
                make_float2(zc.w * fast_tanh(c0), zd.w * fast_tanh(c1));
        }
        __syncthreads();
        xvA = xnA; xvB = xnB; xvC = xnC; xvD = xnD;
    }

    // dense head (4 outputs)
    if (tid == 0) {
        float s = db[0];
#pragma unroll
        for (int k = 0; k < UU; ++k) s += hAB_s[2 * k] * dw[k];
        out[b0] = s;
    } else if (tid == 32) {
        float s = db[0];
#pragma unroll
        for (int k = 0; k < UU; ++k) s += hAB_s[2 * k + 1] * dw[k];
        out[b0 + 1] = s;
    } else if (tid == 64) {
        float s = db[0];
#pragma unroll
        for (int k = 0; k < UU; ++k) s += hCD_s[2 * k] * dw[k];
        out[b0 + 2] = s;
    } else if (tid == 96) {
        float s = db[0];
#pragma unroll
        for (int k = 0; k < UU; ++k) s += hCD_s[2 * k + 1] * dw[k];
        out[b0 + 3] = s;
    }
}

// ---------------------------------------------------------------------------
extern "C" void kernel_launch(void* const* d_in, const int* in_sizes, int n_in,
                              void* d_out, int out_size) {
    const float* x    = (const float*)d_in[0];  // [512,1024,128]
    const float* W    = (const float*)d_in[1];  // [128,200]
    const float* R    = (const float*)d_in[2];  // [50,200]
    const float* bias = (const float*)d_in[3];  // [200]
    const float* dw   = (const float*)d_in[4];  // [50]
    const float* db   = (const float*)d_in[5];  // [1]
    float* out = (float*)d_out;                 // [512]
    (void)in_sizes; (void)n_in; (void)out_size;

    cudaFuncSetAttribute(proj_kernel,
                         cudaFuncAttributeMaxDynamicSharedMemorySize, SMB_TOTAL);

    // Launch period = 2: sampled launch index 3 -> lstm gets profiled.
    proj_kernel<<<NCTA_P, 256, SMB_TOTAL>>>(x, W);
    lstm_kernel<<<BB / 4, 224>>>(R, bias, dw, db, out);
}

// round 14
// speedup vs baseline: 1.8242x; 1.8242x over previous
#include <cuda_runtime.h>
#include <cuda_bf16.h>
#include <math.h>
#include <stdint.h>

// Problem constants
#define BB 512
#define TT 1024
#define FF 128
#define UU 50
#define GG 200            // 4*U gate columns
#define NROWS (BB * TT)   // 524288 GEMM rows
#define MT32 (NROWS / 32) // 16384 m32 tiles
#define NCTA_P 288        // proj CTAs (2 per SM, 3 N-groups x 96)
#define WSTRIDE_P (96 * 8)// m32-tile warp stride per N-group

// Scratch: xproj[b*T + t][200] = x[b,t,:] @ kernel (fp32)
__device__ float g_xproj[(size_t)NROWS * GG];

// ---------------------------------------------------------------------------
// helpers
// ---------------------------------------------------------------------------
__device__ __forceinline__ uint32_t smem_u32(const void* p) {
    uint32_t a;
    asm("{ .reg .u64 t; cvta.to.shared.u64 t, %1; cvt.u32.u64 %0, t; }" : "=r"(a) : "l"(p));
    return a;
}

__device__ __forceinline__ uint32_t bf2pack(float a, float b) {
    __nv_bfloat162 t = __floats2bfloat162_rn(a, b);
    return *reinterpret_cast<uint32_t*>(&t);
}

// pack top 16 bits of two floats into bf16x2 (truncation split, 1 instr)
__device__ __forceinline__ uint32_t hipack(float a, float b) {
    uint32_t d;
    asm("prmt.b32 %0, %1, %2, 0x7632;" : "=r"(d)
        : "r"(__float_as_uint(a)), "r"(__float_as_uint(b)));
    return d;
}
__device__ __forceinline__ float trunc_hi(float v) {
    return __uint_as_float(__float_as_uint(v) & 0xffff0000u);
}

__device__ __forceinline__ void mma16816(float* d, uint32_t a0, uint32_t a1,
                                         uint32_t a2, uint32_t a3,
                                         uint32_t b0, uint32_t b1) {
    asm volatile(
        "mma.sync.aligned.m16n8k16.row.col.f32.bf16.bf16.f32 "
        "{%0,%1,%2,%3}, {%4,%5,%6,%7}, {%8,%9}, {%0,%1,%2,%3};"
        : "+f"(d[0]), "+f"(d[1]), "+f"(d[2]), "+f"(d[3])
        : "r"(a0), "r"(a1), "r"(a2), "r"(a3), "r"(b0), "r"(b1));
}

__device__ __forceinline__ void ldsm_x4(uint32_t& r0, uint32_t& r1,
                                        uint32_t& r2, uint32_t& r3, uint32_t addr) {
    asm volatile("ldmatrix.sync.aligned.m8n8.x4.shared.b16 {%0,%1,%2,%3}, [%4];"
                 : "=r"(r0), "=r"(r1), "=r"(r2), "=r"(r3) : "r"(addr));
}

// packed fp32x2 ops
__device__ __forceinline__ void fma2(uint64_t& d, uint64_t a, uint64_t b) {
    asm("fma.rn.f32x2 %0, %1, %2, %0;" : "+l"(d) : "l"(a), "l"(b));
}
__device__ __forceinline__ void add2(uint64_t& d, uint64_t a) {
    asm("add.rn.f32x2 %0, %0, %1;" : "+l"(d) : "l"(a));
}
__device__ __forceinline__ uint64_t pk2(float lo, float hi) {
    uint64_t r;
    asm("mov.b64 %0, {%1, %2};" : "=l"(r) : "f"(lo), "f"(hi));
    return r;
}
__device__ __forceinline__ void up2(float& lo, float& hi, uint64_t v) {
    asm("mov.b64 {%0, %1}, %2;" : "=f"(lo), "=f"(hi) : "l"(v));
}

__device__ __forceinline__ float fast_tanh(float v) {
    float y;
    asm("tanh.approx.f32 %0, %1;" : "=f"(y) : "f"(v));
    return y;
}
__device__ __forceinline__ float fast_sig(float v) {
    return fmaf(fast_tanh(0.5f * v), 0.5f, 0.5f);
}

// ---------------------------------------------------------------------------
// Kernel 1: projection GEMM xproj = x @ W via HMMA bf16, 3-term hi/lo split.
//   288 CTAs x 256 threads; 3 N-groups; each warp owns an m32 tile with
//   B-fragment reuse across the two m16 halves. [R9-measured: 278.8us]
// ---------------------------------------------------------------------------
#define NT 9                         // n-tiles per CTA group
#define NBROWS (NT * 8)              // 72 B rows staged
#define KP 136                       // padded B row stride in bf16
#define BROW (KP * 2)                // 272 bytes
#define SMB_LO (NBROWS * BROW)       // 19584
#define SMB_TOTAL (2 * NBROWS * BROW)// 39168 bytes

__global__ __launch_bounds__(256, 2)
void proj_kernel(const float* __restrict__ x, const float* __restrict__ W) {
    extern __shared__ char smem[];
    const uint32_t sb = smem_u32(smem);
    const int tid = threadIdx.x;
    const int wid = tid >> 5;
    const int lane = tid & 31;
    const int grpN = blockIdx.x % 3;
    const int noff = grpN * 64;       // global n float-offset of this slice

    for (int idx = tid; idx < NBROWS * FF; idx += 256) {
        int nl = idx >> 7;
        int k = idx & 127;
        float v = W[k * GG + (noff + nl)];
        __nv_bfloat16 hi = __float2bfloat16_rn(v);
        float lo = v - __bfloat162float(hi);
        uint32_t off = (uint32_t)(nl * BROW + k * 2);
        *reinterpret_cast<__nv_bfloat16*>(smem + off) = hi;
        *reinterpret_cast<__nv_bfloat16*>(smem + SMB_LO + off) = __float2bfloat16_rn(lo);
    }
    __syncthreads();

    const int l8 = lane & 7;
    const int grp = lane >> 3;
    const uint32_t lmOff = (uint32_t)(l8 * BROW + (grp & 1) * 16 + (grp >> 1) * SMB_LO);

    const int r = lane >> 2;
    const int cq = lane & 3;

    for (int mt = (blockIdx.x / 3) * 8 + wid; mt < MT32; mt += WSTRIDE_P) {
        const size_t row0 = (size_t)mt * 32 + r;

        const float* __restrict__ p0 = x + row0 * FF;
        const float* __restrict__ p1 = x + (row0 + 8) * FF;
        const float* __restrict__ p2 = x + (row0 + 16) * FF;
        const float* __restrict__ p3 = x + (row0 + 24) * FF;

        float acc0[NT][4], acc1[NT][4];
#pragma unroll
        for (int j = 0; j < NT; ++j) {
#pragma unroll
            for (int q = 0; q < 4; ++q) { acc0[j][q] = 0.f; acc1[j][q] = 0.f; }
        }

#pragma unroll
        for (int kk = 0; kk < 8; ++kk) {
            const int k0 = kk * 16;
            float2 f0 = *(const float2*)(p0 + k0 + 2 * cq);
            float2 f1 = *(const float2*)(p1 + k0 + 2 * cq);
            float2 f2 = *(const float2*)(p0 + k0 + 2 * cq + 8);
            float2 f3 = *(const float2*)(p1 + k0 + 2 * cq + 8);
            float2 g0 = *(const float2*)(p2 + k0 + 2 * cq);
            float2 g1 = *(const float2*)(p3 + k0 + 2 * cq);
            float2 g2 = *(const float2*)(p2 + k0 + 2 * cq + 8);
            float2 g3 = *(const float2*)(p3 + k0 + 2 * cq + 8);

            uint32_t ah0 = hipack(f0.x, f0.y), ah1 = hipack(f1.x, f1.y);
            uint32_t ah2 = hipack(f2.x, f2.y), ah3 = hipack(f3.x, f3.y);
            uint32_t al0 = bf2pack(f0.x - trunc_hi(f0.x), f0.y - trunc_hi(f0.y));
            uint32_t al1 = bf2pack(f1.x - trunc_hi(f1.x), f1.y - trunc_hi(f1.y));
            uint32_t al2 = bf2pack(f2.x - trunc_hi(f2.x), f2.y - trunc_hi(f2.y));
            uint32_t al3 = bf2pack(f3.x - trunc_hi(f3.x), f3.y - trunc_hi(f3.y));

            uint32_t bh0_ = hipack(g0.x, g0.y), bh1_ = hipack(g1.x, g1.y);
            uint32_t bh2_ = hipack(g2.x, g2.y), bh3_ = hipack(g3.x, g3.y);
            uint32_t bl0_ = bf2pack(g0.x - trunc_hi(g0.x), g0.y - trunc_hi(g0.y));
            uint32_t bl1_ = bf2pack(g1.x - trunc_hi(g1.x), g1.y - trunc_hi(g1.y));
            uint32_t bl2_ = bf2pack(g2.x - trunc_hi(g2.x), g2.y - trunc_hi(g2.y));
            uint32_t bl3_ = bf2pack(g3.x - trunc_hi(g3.x), g3.y - trunc_hi(g3.y));

            const uint32_t kOff = sb + (uint32_t)(k0 * 2) + lmOff;
#pragma unroll
            for (int j = 0; j < NT; ++j) {
                uint32_t wh0, wh1, wl0, wl1;
                ldsm_x4(wh0, wh1, wl0, wl1, kOff + (uint32_t)(j * 8 * BROW));
                mma16816(acc0[j], ah0, ah1, ah2, ah3, wh0, wh1);
                mma16816(acc0[j], ah0, ah1, ah2, ah3, wl0, wl1);
                mma16816(acc0[j], al0, al1, al2, al3, wh0, wh1);
                mma16816(acc1[j], bh0_, bh1_, bh2_, bh3_, wh0, wh1);
                mma16816(acc1[j], bh0_, bh1_, bh2_, bh3_, wl0, wl1);
                mma16816(acc1[j], bl0_, bl1_, bl2_, bl3_, wh0, wh1);
            }
        }

        float* __restrict__ d0 = g_xproj + row0 * GG + noff + 2 * cq;
        float* __restrict__ d1 = d0 + 8 * GG;
        float* __restrict__ d2 = d0 + 16 * GG;
        float* __restrict__ d3 = d0 + 24 * GG;
#pragma unroll
        for (int j = 0; j < NT; ++j) {
            *(float2*)(d0 + j * 8) = make_float2(acc0[j][0], acc0[j][1]);
            *(float2*)(d1 + j * 8) = make_float2(acc0[j][2], acc0[j][3]);
            *(float2*)(d2 + j * 8) = make_float2(acc1[j][0], acc1[j][1]);
            *(float2*)(d3 + j * 8) = make_float2(acc1[j][2], acc1[j][3]);
        }
    }
}

// ---------------------------------------------------------------------------
// Kernel 2: LSTM recurrence, f32x2 QUAD-ROW: rows (A,B) and (C,D) each
//   packed element-wise into f32x2 lanes, sharing one set of duplicated
//   weight registers. 128 CTAs x 224 threads.
//   __launch_bounds__(224, 1): full 255-reg budget so the 100-reg weight
//   array stays in registers (R13's bare launch_bounds let ptxas spill
//   it to local at regs=80 -> 2x regression).
//   Per step: 100 fma2 (8 chains), 4 LDG prefetches, 2 barriers = 0.5/row.
// ---------------------------------------------------------------------------
__global__ __launch_bounds__(224, 1)
void lstm_kernel(const float* __restrict__ R, const float* __restrict__ bias,
                 const float* __restrict__ dw, const float* __restrict__ db,
                 float* __restrict__ out) {
    __shared__ __align__(16) float hAB_s[104];   // pairs (hA[k],hB[k])
    __shared__ __align__(16) float hCD_s[104];   // pairs (hC[k],hD[k])
    __shared__ __align__(16) float zA_s[224], zB_s[224], zC_s[224], zD_s[224];

    const int tid = threadIdx.x;
    const int b0 = blockIdx.x * 4;
    const int g = tid & 3;            // gate: 0=i 1=f 2=g~ 3=o
    const int u = tid >> 2;           // unit
    int col = g * 50 + u;
    if (col > 199) col = 199;         // threads 200..223: harmless clamp

    uint64_t rw[UU];                  // duplicated weights (w_k, w_k)
#pragma unroll
    for (int k = 0; k < UU; ++k) {
        float w = R[k * GG + col];
        rw[k] = pk2(w, w);
    }
    const float bv = bias[col];

    for (int i = tid; i < 104; i += 224) { hAB_s[i] = 0.f; hCD_s[i] = 0.f; }
    float c0 = 0.f, c1 = 0.f;   // (cA,cB) in group-1 threads, (cC,cD) in group-2
    __syncthreads();

    const float* __restrict__ xpA = g_xproj + (size_t)b0 * TT * GG;
    const float* __restrict__ xpB = xpA + (size_t)TT * GG;
    const float* __restrict__ xpC = xpB + (size_t)TT * GG;
    const float* __restrict__ xpD = xpC + (size_t)TT * GG;
    float xvA = __ldcs(xpA + col), xvB = __ldcs(xpB + col);
    float xvC = __ldcs(xpC + col), xvD = __ldcs(xpD + col);

#pragma unroll 1
    for (int t = 0; t < TT; ++t) {
        const size_t toff = (size_t)((t + 1 < TT) ? (t + 1) : (TT - 1)) * GG + col;
        float xnA = __ldcs(xpA + toff);
        float xnB = __ldcs(xpB + toff);
        float xnC = __ldcs(xpC + toff);
        float xnD = __ldcs(xpD + toff);

        // quad-row dot: 100 fma2 over pair arrays, 8 independent chains
        uint64_t z2 = pk2(0.f, 0.f);
        uint64_t p0 = z2, p1 = z2, p2 = z2, p3 = z2;   // AB chains
        uint64_t q0 = z2, q1 = z2, q2 = z2, q3 = z2;   // CD chains
#pragma unroll
        for (int i = 0; i < 12; ++i) {
            ulonglong2 a01 = *(const ulonglong2*)(hAB_s + 8 * i);
            ulonglong2 a23 = *(const ulonglong2*)(hAB_s + 8 * i + 4);
            ulonglong2 c01 = *(const ulonglong2*)(hCD_s + 8 * i);
            ulonglong2 c23 = *(const ulonglong2*)(hCD_s + 8 * i + 4);
            fma2(p0, rw[4 * i + 0], a01.x);
            fma2(p1, rw[4 * i + 1], a01.y);
            fma2(p2, rw[4 * i + 2], a23.x);
            fma2(p3, rw[4 * i + 3], a23.y);
            fma2(q0, rw[4 * i + 0], c01.x);
            fma2(q1, rw[4 * i + 1], c01.y);
            fma2(q2, rw[4 * i + 2], c23.x);
            fma2(q3, rw[4 * i + 3], c23.y);
        }
        {
            ulonglong2 at = *(const ulonglong2*)(hAB_s + 96);
            ulonglong2 ct = *(const ulonglong2*)(hCD_s + 96);
            fma2(p0, rw[48], at.x); fma2(p1, rw[49], at.y);
            fma2(q0, rw[48], ct.x); fma2(q1, rw[49], ct.y);
        }
        add2(p0, p1); add2(p2, p3); add2(p0, p2);
        add2(q0, q1); add2(q2, q3); add2(q0, q2);
        float sA, sB, sC, sD;
        up2(sA, sB, p0);
        up2(sC, sD, q0);
        sA += bv + xvA; sB += bv + xvB;
        sC += bv + xvC; sD += bv + xvD;

        if (g == 2) {
            zA_s[tid] = fast_tanh(sA); zB_s[tid] = fast_tanh(sB);
            zC_s[tid] = fast_tanh(sC); zD_s[tid] = fast_tanh(sD);
        } else {
            zA_s[tid] = fast_sig(sA);  zB_s[tid] = fast_sig(sB);
            zC_s[tid] = fast_sig(sC);  zD_s[tid] = fast_sig(sD);
        }
        __syncthreads();

        if (tid < UU) {                       // group 1: rows A,B
            float4 za = *(const float4*)(zA_s + 4 * tid);
            float4 zb = *(const float4*)(zB_s + 4 * tid);
            c0 = fmaf(za.y, c0, za.x * za.z);
            c1 = fmaf(zb.y, c1, zb.x * zb.z);
            *(float2*)(hAB_s + 2 * tid) =
                make_float2(za.w * fast_tanh(c0), zb.w * fast_tanh(c1));
        } else if (tid >= 64 && tid < 64 + UU) { // group 2: rows C,D
            int v = tid - 64;
            float4 zc = *(const float4*)(zC_s + 4 * v);
            float4 zd = *(const float4*)(zD_s + 4 * v);
            c0 = fmaf(zc.y, c0, zc.x * zc.z);
            c1 = fmaf(zd.y, c1, zd.x * zd.z);
            *(float2*)(hCD_s + 2 * v) =
                make_float2(zc.w * fast_tanh(c0), zd.w * fast_tanh(c1));
        }
        __syncthreads();
        xvA = xnA; xvB = xnB; xvC = xnC; xvD = xnD;
    }

    // dense head (4 outputs)
    if (tid == 0) {
        float s = db[0];
#pragma unroll
        for (int k = 0; k < UU; ++k) s += hAB_s[2 * k] * dw[k];
        out[b0] = s;
    } else if (tid == 32) {
        float s = db[0];
#pragma unroll
        for (int k = 0; k < UU; ++k) s += hAB_s[2 * k + 1] * dw[k];
        out[b0 + 1] = s;
    } else if (tid == 64) {
        float s = db[0];
#pragma unroll
        for (int k = 0; k < UU; ++k) s += hCD_s[2 * k] * dw[k];
        out[b0 + 2] = s;
    } else if (tid == 96) {
        float s = db[0];
#pragma unroll
        for (int k = 0; k < UU; ++k) s += hCD_s[2 * k + 1] * dw[k];
        out[b0 + 3] = s;
    }
}

// ---------------------------------------------------------------------------
extern "C" void kernel_launch(void* const* d_in, const int* in_sizes, int n_in,
                              void* d_out, int out_size) {
    const float* x    = (const float*)d_in[0];  // [512,1024,128]
    const float* W    = (const float*)d_in[1];  // [128,200]
    const float* R    = (const float*)d_in[2];  // [50,200]
    const float* bias = (const float*)d_in[3];  // [200]
    const float* dw   = (const float*)d_in[4];  // [50]
    const float* db   = (const float*)d_in[5];  // [1]
    float* out = (float*)d_out;                 // [512]
    (void)in_sizes; (void)n_in; (void)out_size;

    cudaFuncSetAttribute(proj_kernel,
                         cudaFuncAttributeMaxDynamicSharedMemorySize, SMB_TOTAL);

    // Launch period = 2: sampled launch index 3 -> lstm gets profiled.
    proj_kernel<<<NCTA_P, 256, SMB_TOTAL>>>(x, W);
    lstm_kernel<<<BB / 4, 224>>>(R, bias, dw, db, out);
}

// round 16
// speedup vs baseline: 2.0437x; 1.1203x over previous
#include <cuda_runtime.h>
#include <cuda_bf16.h>
#include <math.h>
#include <stdint.h>

// Problem constants
#define BB 512
#define TT 1024
#define FF 128
#define UU 50
#define GG 200            // 4*U gate columns
#define NROWS (BB * TT)   // 524288 GEMM rows
#define MT32 (NROWS / 32) // 16384 m32 tiles
#define NCTA_P 288        // proj CTAs (2 per SM, 3 N-groups x 96)
#define WSTRIDE_P (96 * 8)// m32-tile warp stride per N-group

// Scratch: xproj[b*T + t][200] = x[b,t,:] @ kernel (fp32)
__device__ float g_xproj[(size_t)NROWS * GG];

// ---------------------------------------------------------------------------
// helpers
// ---------------------------------------------------------------------------
__device__ __forceinline__ uint32_t smem_u32(const void* p) {
    uint32_t a;
    asm("{ .reg .u64 t; cvta.to.shared.u64 t, %1; cvt.u32.u64 %0, t; }" : "=r"(a) : "l"(p));
    return a;
}

__device__ __forceinline__ uint32_t bf2pack(float a, float b) {
    __nv_bfloat162 t = __floats2bfloat162_rn(a, b);
    return *reinterpret_cast<uint32_t*>(&t);
}

// pack top 16 bits of two floats into bf16x2 (truncation split, 1 instr)
__device__ __forceinline__ uint32_t hipack(float a, float b) {
    uint32_t d;
    asm("prmt.b32 %0, %1, %2, 0x7632;" : "=r"(d)
        : "r"(__float_as_uint(a)), "r"(__float_as_uint(b)));
    return d;
}
__device__ __forceinline__ float trunc_hi(float v) {
    return __uint_as_float(__float_as_uint(v) & 0xffff0000u);
}

__device__ __forceinline__ void mma16816(float* d, uint32_t a0, uint32_t a1,
                                         uint32_t a2, uint32_t a3,
                                         uint32_t b0, uint32_t b1) {
    asm volatile(
        "mma.sync.aligned.m16n8k16.row.col.f32.bf16.bf16.f32 "
        "{%0,%1,%2,%3}, {%4,%5,%6,%7}, {%8,%9}, {%0,%1,%2,%3};"
        : "+f"(d[0]), "+f"(d[1]), "+f"(d[2]), "+f"(d[3])
        : "r"(a0), "r"(a1), "r"(a2), "r"(a3), "r"(b0), "r"(b1));
}

__device__ __forceinline__ void ldsm_x4(uint32_t& r0, uint32_t& r1,
                                        uint32_t& r2, uint32_t& r3, uint32_t addr) {
    asm volatile("ldmatrix.sync.aligned.m8n8.x4.shared.b16 {%0,%1,%2,%3}, [%4];"
                 : "=r"(r0), "=r"(r1), "=r"(r2), "=r"(r3) : "r"(addr));
}

// packed fp32x2 ops
__device__ __forceinline__ void fma2(uint64_t& d, uint64_t a, uint64_t b) {
    asm("fma.rn.f32x2 %0, %1, %2, %0;" : "+l"(d) : "l"(a), "l"(b));
}
__device__ __forceinline__ void add2(uint64_t& d, uint64_t a) {
    asm("add.rn.f32x2 %0, %0, %1;" : "+l"(d) : "l"(a));
}
__device__ __forceinline__ uint64_t pk2(float lo, float hi) {
    uint64_t r;
    asm("mov.b64 %0, {%1, %2};" : "=l"(r) : "f"(lo), "f"(hi));
    return r;
}
__device__ __forceinline__ void up2(float& lo, float& hi, uint64_t v) {
    asm("mov.b64 {%0, %1}, %2;" : "=f"(lo), "=f"(hi) : "l"(v));
}

__device__ __forceinline__ float fast_tanh(float v) {
    float y;
    asm("tanh.approx.f32 %0, %1;" : "=f"(y) : "f"(v));
    return y;
}
__device__ __forceinline__ float fast_sig(float v) {
    return fmaf(fast_tanh(0.5f * v), 0.5f, 0.5f);
}

// ---------------------------------------------------------------------------
// Kernel 1: projection GEMM xproj = x @ W via HMMA bf16, 3-term hi/lo split.
//   288 CTAs x 256 threads; 3 N-groups; each warp owns an m32 tile with
//   B-fragment reuse across the two m16 halves. [R9-measured: 278.8us]
// ---------------------------------------------------------------------------
#define NT 9                         // n-tiles per CTA group
#define NBROWS (NT * 8)              // 72 B rows staged
#define KP 136                       // padded B row stride in bf16
#define BROW (KP * 2)                // 272 bytes
#define SMB_LO (NBROWS * BROW)       // 19584
#define SMB_TOTAL (2 * NBROWS * BROW)// 39168 bytes

__global__ __launch_bounds__(256, 2)
void proj_kernel(const float* __restrict__ x, const float* __restrict__ W) {
    extern __shared__ char smem[];
    const uint32_t sb = smem_u32(smem);
    const int tid = threadIdx.x;
    const int wid = tid >> 5;
    const int lane = tid & 31;
    const int grpN = blockIdx.x % 3;
    const int noff = grpN * 64;       // global n float-offset of this slice

    for (int idx = tid; idx < NBROWS * FF; idx += 256) {
        int nl = idx >> 7;
        int k = idx & 127;
        float v = W[k * GG + (noff + nl)];
        __nv_bfloat16 hi = __float2bfloat16_rn(v);
        float lo = v - __bfloat162float(hi);
        uint32_t off = (uint32_t)(nl * BROW + k * 2);
        *reinterpret_cast<__nv_bfloat16*>(smem + off) = hi;
        *reinterpret_cast<__nv_bfloat16*>(smem + SMB_LO + off) = __float2bfloat16_rn(lo);
    }
    __syncthreads();

    const int l8 = lane & 7;
    const int grp = lane >> 3;
    const uint32_t lmOff = (uint32_t)(l8 * BROW + (grp & 1) * 16 + (grp >> 1) * SMB_LO);

    const int r = lane >> 2;
    const int cq = lane & 3;

    for (int mt = (blockIdx.x / 3) * 8 + wid; mt < MT32; mt += WSTRIDE_P) {
        const size_t row0 = (size_t)mt * 32 + r;

        const float* __restrict__ p0 = x + row0 * FF;
        const float* __restrict__ p1 = x + (row0 + 8) * FF;
        const float* __restrict__ p2 = x + (row0 + 16) * FF;
        const float* __restrict__ p3 = x + (row0 + 24) * FF;

        float acc0[NT][4], acc1[NT][4];
#pragma unroll
        for (int j = 0; j < NT; ++j) {
#pragma unroll
            for (int q = 0; q < 4; ++q) { acc0[j][q] = 0.f; acc1[j][q] = 0.f; }
        }

#pragma unroll
        for (int kk = 0; kk < 8; ++kk) {
            const int k0 = kk * 16;
            float2 f0 = *(const float2*)(p0 + k0 + 2 * cq);
            float2 f1 = *(const float2*)(p1 + k0 + 2 * cq);
            float2 f2 = *(const float2*)(p0 + k0 + 2 * cq + 8);
            float2 f3 = *(const float2*)(p1 + k0 + 2 * cq + 8);
            float2 g0 = *(const float2*)(p2 + k0 + 2 * cq);
            float2 g1 = *(const float2*)(p3 + k0 + 2 * cq);
            float2 g2 = *(const float2*)(p2 + k0 + 2 * cq + 8);
            float2 g3 = *(const float2*)(p3 + k0 + 2 * cq + 8);

            uint32_t ah0 = hipack(f0.x, f0.y), ah1 = hipack(f1.x, f1.y);
            uint32_t ah2 = hipack(f2.x, f2.y), ah3 = hipack(f3.x, f3.y);
            uint32_t al0 = bf2pack(f0.x - trunc_hi(f0.x), f0.y - trunc_hi(f0.y));
            uint32_t al1 = bf2pack(f1.x - trunc_hi(f1.x), f1.y - trunc_hi(f1.y));
            uint32_t al2 = bf2pack(f2.x - trunc_hi(f2.x), f2.y - trunc_hi(f2.y));
            uint32_t al3 = bf2pack(f3.x - trunc_hi(f3.x), f3.y - trunc_hi(f3.y));

            uint32_t bh0_ = hipack(g0.x, g0.y), bh1_ = hipack(g1.x, g1.y);
            uint32_t bh2_ = hipack(g2.x, g2.y), bh3_ = hipack(g3.x, g3.y);
            uint32_t bl0_ = bf2pack(g0.x - trunc_hi(g0.x), g0.y - trunc_hi(g0.y));
            uint32_t bl1_ = bf2pack(g1.x - trunc_hi(g1.x), g1.y - trunc_hi(g1.y));
            uint32_t bl2_ = bf2pack(g2.x - trunc_hi(g2.x), g2.y - trunc_hi(g2.y));
            uint32_t bl3_ = bf2pack(g3.x - trunc_hi(g3.x), g3.y - trunc_hi(g3.y));

            const uint32_t kOff = sb + (uint32_t)(k0 * 2) + lmOff;
#pragma unroll
            for (int j = 0; j < NT; ++j) {
                uint32_t wh0, wh1, wl0, wl1;
                ldsm_x4(wh0, wh1, wl0, wl1, kOff + (uint32_t)(j * 8 * BROW));
                mma16816(acc0[j], ah0, ah1, ah2, ah3, wh0, wh1);
                mma16816(acc0[j], ah0, ah1, ah2, ah3, wl0, wl1);
                mma16816(acc0[j], al0, al1, al2, al3, wh0, wh1);
                mma16816(acc1[j], bh0_, bh1_, bh2_, bh3_, wh0, wh1);
                mma16816(acc1[j], bh0_, bh1_, bh2_, bh3_, wl0, wl1);
                mma16816(acc1[j], bl0_, bl1_, bl2_, bl3_, wh0, wh1);
            }
        }

        float* __restrict__ d0 = g_xproj + row0 * GG + noff + 2 * cq;
        float* __restrict__ d1 = d0 + 8 * GG;
        float* __restrict__ d2 = d0 + 16 * GG;
        float* __restrict__ d3 = d0 + 24 * GG;
#pragma unroll
        for (int j = 0; j < NT; ++j) {
            *(float2*)(d0 + j * 8) = make_float2(acc0[j][0], acc0[j][1]);
            *(float2*)(d1 + j * 8) = make_float2(acc0[j][2], acc0[j][3]);
            *(float2*)(d2 + j * 8) = make_float2(acc1[j][0], acc1[j][1]);
            *(float2*)(d3 + j * 8) = make_float2(acc1[j][2], acc1[j][3]);
        }
    }
}

// ---------------------------------------------------------------------------
// Kernel 2: LSTM recurrence, f32x2 dual-row + quad-shuffle update, with
//   DOUBLE-BUFFERED h (fixes R15's WAR race: fast warps were overwriting h
//   while slow warps still read it). 256 CTAs x 224 threads (2 CTAs/SM).
//   Thread (u=tid>>2, g=tid&3) owns gate column g*50+u -> unit u's 4 gates
//   live in one shuffle quad. ONE barrier per step.
// ---------------------------------------------------------------------------
__global__ __launch_bounds__(224, 2)
void lstm_kernel(const float* __restrict__ R, const float* __restrict__ bias,
                 const float* __restrict__ dw, const float* __restrict__ db,
                 float* __restrict__ out) {
    __shared__ __align__(16) float hAB_s[2][104];  // pairs (hA[k],hB[k]), x2 buffers

    const int tid = threadIdx.x;
    const int b0 = blockIdx.x * 2;
    const int g = tid & 3;            // gate: 0=i 1=f 2=g~ 3=o
    const int u = tid >> 2;           // unit
    int col = g * 50 + u;
    if (col > 199) col = 199;         // threads 200..223: harmless clamp
    const int lane = tid & 31;
    const int q0 = lane & ~3;         // quad base lane
    const bool writer = (g == 0) && (u < UU);

    uint64_t rw[UU];                  // duplicated weights (w_k, w_k)
#pragma unroll
    for (int k = 0; k < UU; ++k) {
        float w = R[k * GG + col];
        rw[k] = pk2(w, w);
    }
    const float bv = bias[col];

    for (int i = tid; i < 104; i += 224) { hAB_s[0][i] = 0.f; hAB_s[1][i] = 0.f; }
    float cA = 0.f, cB = 0.f;
    __syncthreads();

    const float* __restrict__ xpA = g_xproj + (size_t)b0 * TT * GG;
    const float* __restrict__ xpB = xpA + (size_t)TT * GG;
    float xvA = __ldcs(xpA + col);
    float xvB = __ldcs(xpB + col);

#pragma unroll 1
    for (int t = 0; t < TT; ++t) {
        const float* __restrict__ hr = hAB_s[t & 1];        // read buffer
        float* __restrict__ hw = hAB_s[(t & 1) ^ 1];        // write buffer

        const size_t toff = (size_t)((t + 1 < TT) ? (t + 1) : (TT - 1)) * GG + col;
        float xnA = __ldcs(xpA + toff);
        float xnB = __ldcs(xpB + toff);

        // dual-row dot: 50 fma2 over pairs (hA[k],hB[k]), 4 chains
        uint64_t z2 = pk2(0.f, 0.f);
        uint64_t a0 = z2, a1 = z2, a2 = z2, a3 = z2;
#pragma unroll
        for (int i = 0; i < 12; ++i) {
            ulonglong2 h01 = *(const ulonglong2*)(hr + 8 * i);
            ulonglong2 h23 = *(const ulonglong2*)(hr + 8 * i + 4);
            fma2(a0, rw[4 * i + 0], h01.x);
            fma2(a1, rw[4 * i + 1], h01.y);
            fma2(a2, rw[4 * i + 2], h23.x);
            fma2(a3, rw[4 * i + 3], h23.y);
        }
        {
            ulonglong2 ht = *(const ulonglong2*)(hr + 96);
            fma2(a0, rw[48], ht.x);
            fma2(a1, rw[49], ht.y);
        }
        add2(a0, a1); add2(a2, a3); add2(a0, a2);
        float sA, sB;
        up2(sA, sB, a0);
        sA += bv + xvA;
        sB += bv + xvB;

        float zA, zB;
        if (g == 2) { zA = fast_tanh(sA); zB = fast_tanh(sB); }
        else        { zA = fast_sig(sA);  zB = fast_sig(sB); }

        // gather the quad's 4 gate values for both rows
        float ziA = __shfl_sync(0xFFFFFFFFu, zA, q0 + 0);
        float zfA = __shfl_sync(0xFFFFFFFFu, zA, q0 + 1);
        float zgA = __shfl_sync(0xFFFFFFFFu, zA, q0 + 2);
        float zoA = __shfl_sync(0xFFFFFFFFu, zA, q0 + 3);
        float ziB = __shfl_sync(0xFFFFFFFFu, zB, q0 + 0);
        float zfB = __shfl_sync(0xFFFFFFFFu, zB, q0 + 1);
        float zgB = __shfl_sync(0xFFFFFFFFu, zB, q0 + 2);
        float zoB = __shfl_sync(0xFFFFFFFFu, zB, q0 + 3);

        cA = fmaf(zfA, cA, ziA * zgA);
        cB = fmaf(zfB, cB, ziB * zgB);
        float hA = zoA * fast_tanh(cA);
        float hB = zoB * fast_tanh(cB);
        if (writer) *(float2*)(hw + 2 * u) = make_float2(hA, hB);

        __syncthreads();
        xvA = xnA; xvB = xnB;
    }

    // dense head: final h was written in t=1023 -> buffer (1023&1)^1 = 0
    if (tid == 0) {
        float s = db[0];
#pragma unroll
        for (int k = 0; k < UU; ++k) s += hAB_s[0][2 * k] * dw[k];
        out[b0] = s;
    } else if (tid == 32) {
        float s = db[0];
#pragma unroll
        for (int k = 0; k < UU; ++k) s += hAB_s[0][2 * k + 1] * dw[k];
        out[b0 + 1] = s;
    }
}

// ---------------------------------------------------------------------------
extern "C" void kernel_launch(void* const* d_in, const int* in_sizes, int n_in,
                              void* d_out, int out_size) {
    const float* x    = (const float*)d_in[0];  // [512,1024,128]
    const float* W    = (const float*)d_in[1];  // [128,200]
    const float* R    = (const float*)d_in[2];  // [50,200]
    const float* bias = (const float*)d_in[3];  // [200]
    const float* dw   = (const float*)d_in[4];  // [50]
    const float* db   = (const float*)d_in[5];  // [1]
    float* out = (float*)d_out;                 // [512]
    (void)in_sizes; (void)n_in; (void)out_size;

    cudaFuncSetAttribute(proj_kernel,
                         cudaFuncAttributeMaxDynamicSharedMemorySize, SMB_TOTAL);

    // Launch period = 2: sampled launch index 3 -> lstm gets profiled.
    proj_kernel<<<NCTA_P, 256, SMB_TOTAL>>>(x, W);
    lstm_kernel<<<BB / 2, 224>>>(R, bias, dw, db, out);
}